// round 3
// baseline (speedup 1.0000x reference)
#include <cuda_runtime.h>
#include <math.h>

#define NCODES 16384
#define CEMB   64
#define BB     8
#define TT     4
#define ZSIZE  (BB*CEMB*TT*16*16)   /* 524288 */
#define MAXN   8192

#define OFF_COMMIT 524288
#define OFF_PERP   524289
#define OFF_AVG    524290
#define OFF_USAGE  524291
#define OFF_IDX    540675

__device__ float g_accu[ZSIZE];
__device__ float g_hup[ZSIZE];
__device__ float g_q[MAXN*CEMB];
__device__ unsigned long long g_key[MAXN];
__device__ int   g_idx[MAXN];
__device__ float g_embT[CEMB*NCODES];
__device__ float g_esq[NCODES];
__device__ float g_Wt[4*64*64*27];
__device__ float g_commit;
__device__ int   g_counts[NCODES];

// ---------------- setup ----------------
__global__ void k_prep_emb(const float* __restrict__ emb) {
    int tid = blockIdx.x*256 + threadIdx.x;
    if (tid < CEMB*NCODES) {
        int k = tid >> 14, c = tid & (NCODES-1);
        g_embT[tid] = emb[c*CEMB + k];
    }
}

__global__ void k_esq(const float* __restrict__ emb) {
    int c = blockIdx.x*256 + threadIdx.x;
    if (c < NCODES) {
        const float4* p = reinterpret_cast<const float4*>(emb + c*CEMB);
        float s = 0.f;
        #pragma unroll
        for (int i = 0; i < 16; i++) {
            float4 v = p[i];
            s += v.x*v.x + v.y*v.y + v.z*v.z + v.w*v.w;
        }
        g_esq[c] = s;
    }
}

__global__ void k_prep_w(const float* __restrict__ Wq) {
    int tid = blockIdx.x*256 + threadIdx.x;
    if (tid < 4*64*64*27) {
        int k  = tid % 27;
        int t2 = tid / 27;
        int c  = t2 % 64;
        int t3 = t2 / 64;
        int ci = t3 % 64;
        int q  = t3 / 64;
        g_Wt[tid] = Wq[((q*64 + c)*64 + ci)*27 + k];
    }
}

__global__ void k_zero() {
    int tid = blockIdx.x*256 + threadIdx.x;
    if (tid < ZSIZE) g_accu[tid] = 0.f;
    if (tid < NCODES) g_counts[tid] = 0;
    if (tid == 0) g_commit = 0.f;
}

// ---------------- per-scale: pool (z - accu) -> query buffer [N][64] ----------------
__global__ void k_pool(const float* __restrict__ z, int tpn, int pn, int N) {
    int tid = blockIdx.x*256 + threadIdx.x;
    if (tid >= N*64) return;
    int c = tid & 63;
    int n = tid >> 6;
    int x = n % pn;
    int v = (n/pn) % pn;
    int r2 = n/(pn*pn);
    int u = r2 % tpn;
    int b = r2 / tpn;
    int sT = (u*4)/tpn,  eT = ((u+1)*4  + tpn-1)/tpn;
    int sH = (v*16)/pn,  eH = ((v+1)*16 + pn-1)/pn;
    int sW = (x*16)/pn,  eW = ((x+1)*16 + pn-1)/pn;
    const float* zp = z      + (b*64 + c)*1024;
    const float* ap = g_accu + (b*64 + c)*1024;
    float sum = 0.f;
    for (int t = sT; t < eT; t++)
        for (int h = sH; h < eH; h++)
            for (int w = sW; w < eW; w++) {
                int o = t*256 + h*16 + w;
                sum += zp[o] - ap[o];
            }
    float inv = (1.f/(float)(eT-sT))*(1.f/(float)(eH-sH))*(1.f/(float)(eW-sW));
    g_q[n*64 + c] = sum * inv;
}

__global__ void k_init(int N) {
    int n = blockIdx.x*256 + threadIdx.x;
    if (n < N) g_key[n] = 0xFFFFFFFFFFFFFFFFull;
}

// ---------------- NN search: 32 queries x 256 codes per block ----------------
__global__ void __launch_bounds__(256) k_nn(int N) {
    int tx = threadIdx.x;            // 0..63 (code lanes)
    int ty = threadIdx.y;            // 0..3  (query groups of 8)
    int qbase = blockIdx.y << 5;
    int cbase = (blockIdx.x << 8) + (tx << 2);
    __shared__ float qs[32*64];
    int tid = ty*64 + tx;
    for (int i = tid; i < 2048; i += 256) {
        int qr = qbase + (i >> 6);
        qs[i] = (qr < N) ? g_q[qr*64 + (i & 63)] : 0.f;
    }
    __syncthreads();
    float acc[8][4];
    #pragma unroll
    for (int j = 0; j < 8; j++)
        #pragma unroll
        for (int cc = 0; cc < 4; cc++) acc[j][cc] = 0.f;
    const float4* e4 = reinterpret_cast<const float4*>(g_embT);
    int coff = (blockIdx.x << 6) + tx;
    const float* qb = qs + (ty << 3)*64;
    #pragma unroll 4
    for (int k = 0; k < 64; k++) {
        float4 ev = e4[(k << 12) + coff];
        #pragma unroll
        for (int j = 0; j < 8; j++) {
            float qv = qb[j*64 + k];
            acc[j][0] = fmaf(qv, ev.x, acc[j][0]);
            acc[j][1] = fmaf(qv, ev.y, acc[j][1]);
            acc[j][2] = fmaf(qv, ev.z, acc[j][2]);
            acc[j][3] = fmaf(qv, ev.w, acc[j][3]);
        }
    }
    float es0 = g_esq[cbase+0], es1 = g_esq[cbase+1];
    float es2 = g_esq[cbase+2], es3 = g_esq[cbase+3];
    #pragma unroll
    for (int j = 0; j < 8; j++) {
        float s0 = fmaf(-2.f, acc[j][0], es0);
        float s1 = fmaf(-2.f, acc[j][1], es1);
        float s2 = fmaf(-2.f, acc[j][2], es2);
        float s3 = fmaf(-2.f, acc[j][3], es3);
        float best = s0; int bi = cbase;
        if (s1 < best) { best = s1; bi = cbase+1; }
        if (s2 < best) { best = s2; bi = cbase+2; }
        if (s3 < best) { best = s3; bi = cbase+3; }
        unsigned ub = __float_as_uint(best);
        ub = (ub & 0x80000000u) ? ~ub : (ub | 0x80000000u);
        unsigned long long key = ((unsigned long long)ub << 32) | (unsigned)bi;
        #pragma unroll
        for (int o = 16; o; o >>= 1) {
            unsigned long long ok = __shfl_down_sync(0xffffffffu, key, o);
            if (ok < key) key = ok;
        }
        if ((tx & 31) == 0) {
            int q = qbase + (ty << 3) + j;
            if (q < N) atomicMin(&g_key[q], key);
        }
    }
}

__global__ void k_extract(int N, float* __restrict__ outp) {
    int n = blockIdx.x*256 + threadIdx.x;
    if (n < N) {
        int id = (int)(g_key[n] & 0xffffffffull);
        g_idx[n] = id;
        outp[n] = (float)id;
    }
}

// ---------------- upsample (trilinear, align_corners=False) ----------------
__device__ __forceinline__ void axw(int i, int in, int out, int& i0, int& i1, float& f) {
    float scale = (float)in / (float)out;
    float src = fmaxf((i + 0.5f)*scale - 0.5f, 0.f);
    i0 = (int)src;                     // floor (src >= 0)
    if (i0 > in-1) i0 = in-1;
    i1 = i0 + 1; if (i1 > in-1) i1 = in-1;
    f = src - (float)i0;
}

__global__ void k_upsample(const float* __restrict__ emb, int tpn, int pn) {
    int tid = blockIdx.x*256 + threadIdx.x;
    if (tid >= ZSIZE) return;
    int w = tid & 15, h = (tid >> 4) & 15, t = (tid >> 8) & 3;
    int c = (tid >> 10) & 63, b = tid >> 16;
    int t0,t1,h0,h1,w0,w1; float ft,fh,fw;
    axw(t, tpn,  4, t0, t1, ft);
    axw(h, pn,  16, h0, h1, fh);
    axw(w, pn,  16, w0, w1, fw);
    int ts[2]  = {t0, t1}; float twt[2] = {1.f-ft, ft};
    int hs[2]  = {h0, h1}; float hwt[2] = {1.f-fh, fh};
    int wss[2] = {w0, w1}; float wwt[2] = {1.f-fw, fw};
    int nb = b*tpn;
    float v = 0.f;
    #pragma unroll
    for (int a = 0; a < 2; a++)
        #pragma unroll
        for (int d = 0; d < 2; d++)
            #pragma unroll
            for (int e = 0; e < 2; e++) {
                float wt = twt[a]*hwt[d]*wwt[e];
                int n = ((nb + ts[a])*pn + hs[d])*pn + wss[e];
                v += wt * emb[g_idx[n]*64 + c];
            }
    g_hup[tid] = v;
}

// ---------------- conv3d 3x3x3 SAME + residual mix + accumulate + commit ----------------
__global__ void __launch_bounds__(256) k_conv(const float* __restrict__ z,
                                              const float* __restrict__ bq, int qi) {
    int b = blockIdx.x, t = blockIdx.y, hq = blockIdx.z;
    int tid = threadIdx.x;
    int c = tid & 63, hh = tid >> 6;
    int h = hq*4 + hh;
    __shared__ float xs[288];      // [3 t][6 h][16 w]
    __shared__ float ws[1728];     // [64 c][27 k]
    __shared__ float red[8];
    float acc[16];
    #pragma unroll
    for (int i = 0; i < 16; i++) acc[i] = 0.f;
    for (int ci = 0; ci < 64; ci++) {
        __syncthreads();
        const float* wsrc = g_Wt + (size_t)((qi*64 + ci)*64)*27;
        for (int i = tid; i < 1728; i += 256) ws[i] = wsrc[i];
        for (int i = tid; i < 288; i += 256) {   // FIX: 288 > blockDim, must stride
            int td = i/96, rem = i%96, hd = rem/16, wd = rem & 15;
            int tt = t + td - 1;
            int hg = hq*4 + hd - 1;
            xs[i] = (tt >= 0 && tt < 4 && hg >= 0 && hg < 16)
                      ? g_hup[((b*64 + ci)*4 + tt)*256 + hg*16 + wd] : 0.f;
        }
        __syncthreads();
        #pragma unroll
        for (int kd = 0; kd < 3; kd++) {
            #pragma unroll
            for (int kh = 0; kh < 3; kh++) {
                float r[18];
                r[0] = 0.f; r[17] = 0.f;
                const float* xrow = xs + (kd*6 + hh + kh)*16;
                #pragma unroll
                for (int i2 = 0; i2 < 16; i2++) r[i2+1] = xrow[i2];
                const float* wp = ws + c*27 + kd*9 + kh*3;
                #pragma unroll
                for (int kw = 0; kw < 3; kw++) {
                    float wv = wp[kw];
                    #pragma unroll
                    for (int w2 = 0; w2 < 16; w2++)
                        acc[w2] = fmaf(wv, r[w2+kw], acc[w2]);
                }
            }
        }
    }
    float bias = bq[qi*64 + c];
    int base = ((b*64 + c)*4 + t)*256 + h*16;
    float lsum = 0.f;
    #pragma unroll
    for (int w2 = 0; w2 < 16; w2++) {
        float hv = g_hup[base + w2];
        float val = 0.5f*hv + 0.5f*(acc[w2] + bias);
        float a = g_accu[base + w2] + val;
        g_accu[base + w2] = a;
        float d = a - z[base + w2];
        lsum = fmaf(d, d, lsum);
    }
    #pragma unroll
    for (int o = 16; o; o >>= 1) lsum += __shfl_down_sync(0xffffffffu, lsum, o);
    if ((tid & 31) == 0) red[tid >> 5] = lsum;
    __syncthreads();
    if (tid < 8) {
        float v = red[tid];
        #pragma unroll
        for (int o = 4; o; o >>= 1) v += __shfl_down_sync(0xffu, v, o);
        if (tid == 0) atomicAdd(&g_commit, v);
    }
}

// ---------------- finalization ----------------
__global__ void k_bincount() {
    int n = blockIdx.x*256 + threadIdx.x;
    if (n < 8192) atomicAdd(&g_counts[g_idx[n]], 1);
}

__global__ void k_copy(const float* __restrict__ z, float* __restrict__ out) {
    int i = blockIdx.x*256 + threadIdx.x;
    if (i < ZSIZE) out[i] = (g_accu[i] - z[i]) + z[i];  // straight-through, match ref rounding
}

__global__ void k_stats(float* __restrict__ out) {
    int tid = threadIdx.x;
    float ent = 0.f; int cnt = 0;
    for (int i = tid; i < NCODES; i += 256) {
        float p = (float)g_counts[i] * (1.0f/8192.0f);
        out[OFF_USAGE + i] = p;
        ent += p * logf(p + 1e-10f);
        if (p > (1.0f/16384.0f)) cnt++;
    }
    __shared__ float se[256];
    __shared__ int   sc[256];
    se[tid] = ent; sc[tid] = cnt;
    __syncthreads();
    for (int o = 128; o; o >>= 1) {
        if (tid < o) { se[tid] += se[tid+o]; sc[tid] += sc[tid+o]; }
        __syncthreads();
    }
    if (tid == 0) {
        out[OFF_COMMIT] = g_commit * (0.25f/524288.0f) * 0.1f;
        out[OFF_PERP]   = expf(-se[0]);
        out[OFF_AVG]    = (float)sc[0] / 16384.0f;
    }
}

extern "C" void kernel_launch(void* const* d_in, const int* in_sizes, int n_in,
                              void* d_out, int out_size) {
    // Bind inputs by element count (robust to metadata ordering):
    //   z = 524288, embeddings = 1048576, Wq = 442368, bq = 256
    const float* z   = nullptr;
    const float* emb = nullptr;
    const float* Wq  = nullptr;
    const float* bq  = nullptr;
    for (int i = 0; i < n_in; i++) {
        switch (in_sizes[i]) {
            case 524288:  z   = (const float*)d_in[i]; break;
            case 1048576: emb = (const float*)d_in[i]; break;
            case 442368:  Wq  = (const float*)d_in[i]; break;
            case 256:     bq  = (const float*)d_in[i]; break;
        }
    }
    float* out = (float*)d_out;

    k_prep_emb<<<(CEMB*NCODES + 255)/256, 256>>>(emb);
    k_esq<<<(NCODES + 255)/256, 256>>>(emb);
    k_prep_w<<<(4*64*64*27 + 255)/256, 256>>>(Wq);
    k_zero<<<(ZSIZE + 255)/256, 256>>>();

    static const int TPN[10] = {1,1,2,2,2,4,4,4,4,4};
    static const int VPN[10] = {1,2,3,4,5,6,8,10,13,16};
    static const int QIA[10] = {0,0,1,1,1,2,2,3,3,3};

    int off = OFF_IDX;
    for (int si = 0; si < 10; si++) {
        int tpn = TPN[si], pn = VPN[si];
        int N = BB * tpn * pn * pn;
        k_pool<<<(N*64 + 255)/256, 256>>>(z, tpn, pn, N);
        k_init<<<(N + 255)/256, 256>>>(N);
        dim3 gnn(64, (N + 31)/32), bnn(64, 4);
        k_nn<<<gnn, bnn>>>(N);
        k_extract<<<(N + 255)/256, 256>>>(N, out + off);
        off += N;
        k_upsample<<<(ZSIZE + 255)/256, 256>>>(emb, tpn, pn);
        k_conv<<<dim3(8,4,4), 256>>>(z, bq, QIA[si]);
    }
    k_bincount<<<32, 256>>>();
    k_copy<<<(ZSIZE + 255)/256, 256>>>(z, out);
    k_stats<<<1, 256>>>(out);
}

// round 4
// speedup vs baseline: 1.0504x; 1.0504x over previous
#include <cuda_runtime.h>
#include <math.h>

#define NCODES 16384
#define CEMB   64
#define BB     8
#define ZSIZE  (BB*CEMB*4*16*16)   /* 524288 */
#define MAXN   8192

#define OFF_COMMIT 524288
#define OFF_PERP   524289
#define OFF_AVG    524290
#define OFF_USAGE  524291
#define OFF_IDX    540675

__device__ float g_accu[ZSIZE];
__device__ float g_hup[ZSIZE];
__device__ float g_q[MAXN*CEMB];
__device__ unsigned long long g_key[MAXN];
__device__ float g_embT[CEMB*NCODES];
__device__ float g_esq[NCODES];
__device__ float g_Wt[4*64*64*27];
__device__ float g_commit;
__device__ int   g_counts[NCODES];

// ---------------- setup ----------------
__global__ void k_prep_emb(const float* __restrict__ emb) {
    int tid = blockIdx.x*256 + threadIdx.x;
    if (tid < CEMB*NCODES) {
        int k = tid >> 14, c = tid & (NCODES-1);
        g_embT[tid] = emb[c*CEMB + k];
    }
}

__global__ void k_esq(const float* __restrict__ emb) {
    int c = blockIdx.x*256 + threadIdx.x;
    if (c < NCODES) {
        const float4* p = reinterpret_cast<const float4*>(emb + c*CEMB);
        float s = 0.f;
        #pragma unroll
        for (int i = 0; i < 16; i++) {
            float4 v = p[i];
            s += v.x*v.x + v.y*v.y + v.z*v.z + v.w*v.w;
        }
        g_esq[c] = s;
    }
}

__global__ void k_prep_w(const float* __restrict__ Wq) {
    int tid = blockIdx.x*256 + threadIdx.x;
    if (tid < 4*64*64*27) {
        int k  = tid % 27;
        int t2 = tid / 27;
        int c  = t2 % 64;
        int t3 = t2 / 64;
        int ci = t3 % 64;
        int q  = t3 / 64;
        g_Wt[tid] = Wq[((q*64 + c)*64 + ci)*27 + k];
    }
}

__global__ void k_zero() {
    int tid = blockIdx.x*256 + threadIdx.x;
    if (tid < ZSIZE) g_accu[tid] = 0.f;
    if (tid < NCODES) g_counts[tid] = 0;
    if (tid == 0) g_commit = 0.f;
}

// -------- per-scale: pool (z - accu) -> queries [N][64]; also init keys --------
__global__ void k_pool(const float* __restrict__ z, int tpn, int pn, int N) {
    int tid = blockIdx.x*256 + threadIdx.x;
    if (tid >= N*64) return;
    int c = tid & 63;
    int n = tid >> 6;
    if (c == 0) g_key[n] = 0xFFFFFFFFFFFFFFFFull;   // fused k_init
    int x = n % pn;
    int v = (n/pn) % pn;
    int r2 = n/(pn*pn);
    int u = r2 % tpn;
    int b = r2 / tpn;
    int sT = (u*4)/tpn,  eT = ((u+1)*4  + tpn-1)/tpn;
    int sH = (v*16)/pn,  eH = ((v+1)*16 + pn-1)/pn;
    int sW = (x*16)/pn,  eW = ((x+1)*16 + pn-1)/pn;
    const float* zp = z      + (b*64 + c)*1024;
    const float* ap = g_accu + (b*64 + c)*1024;
    float sum = 0.f;
    for (int t = sT; t < eT; t++)
        for (int h = sH; h < eH; h++)
            for (int w = sW; w < eW; w++) {
                int o = t*256 + h*16 + w;
                sum += zp[o] - ap[o];
            }
    float inv = (1.f/(float)(eT-sT))*(1.f/(float)(eH-sH))*(1.f/(float)(eW-sW));
    g_q[n*64 + c] = sum * inv;
}

// -------- NN search: 32 queries x 512 codes per block, 8x8 per thread --------
__global__ void __launch_bounds__(256) k_nn(int N) {
    int tx = threadIdx.x;            // 0..63 (8 codes each)
    int ty = threadIdx.y;            // 0..3  (8 queries each)
    int qbase = blockIdx.y << 5;
    int cbase = (blockIdx.x << 9) + (tx << 3);
    __shared__ float qs[32*64];
    int tid = ty*64 + tx;
    for (int i = tid; i < 2048; i += 256) {
        int qr = qbase + (i >> 6);
        qs[i] = (qr < N) ? g_q[qr*64 + (i & 63)] : 0.f;
    }
    __syncthreads();
    float acc[8][8];
    #pragma unroll
    for (int j = 0; j < 8; j++)
        #pragma unroll
        for (int cc = 0; cc < 8; cc++) acc[j][cc] = 0.f;
    const float4* e4 = reinterpret_cast<const float4*>(g_embT);
    int coff = (blockIdx.x << 7) + (tx << 1);
    const float* qb = qs + (ty << 3)*64;
    #pragma unroll 4
    for (int k = 0; k < 64; k++) {
        float4 ea = e4[(k << 12) + coff];
        float4 eb = e4[(k << 12) + coff + 1];
        #pragma unroll
        for (int j = 0; j < 8; j++) {
            float qv = qb[j*64 + k];
            acc[j][0] = fmaf(qv, ea.x, acc[j][0]);
            acc[j][1] = fmaf(qv, ea.y, acc[j][1]);
            acc[j][2] = fmaf(qv, ea.z, acc[j][2]);
            acc[j][3] = fmaf(qv, ea.w, acc[j][3]);
            acc[j][4] = fmaf(qv, eb.x, acc[j][4]);
            acc[j][5] = fmaf(qv, eb.y, acc[j][5]);
            acc[j][6] = fmaf(qv, eb.z, acc[j][6]);
            acc[j][7] = fmaf(qv, eb.w, acc[j][7]);
        }
    }
    const float4* s4 = reinterpret_cast<const float4*>(g_esq);
    float4 qa = s4[cbase >> 2];
    float4 qbv = s4[(cbase >> 2) + 1];
    float es[8] = {qa.x, qa.y, qa.z, qa.w, qbv.x, qbv.y, qbv.z, qbv.w};
    #pragma unroll
    for (int j = 0; j < 8; j++) {
        float best = 3.4e38f; int bi = 0;
        #pragma unroll
        for (int cc = 0; cc < 8; cc++) {
            float s = fmaf(-2.f, acc[j][cc], es[cc]);
            if (s < best) { best = s; bi = cbase + cc; }
        }
        unsigned ub = __float_as_uint(best);
        ub = (ub & 0x80000000u) ? ~ub : (ub | 0x80000000u);
        unsigned long long key = ((unsigned long long)ub << 32) | (unsigned)bi;
        #pragma unroll
        for (int o = 16; o; o >>= 1) {
            unsigned long long ok = __shfl_down_sync(0xffffffffu, key, o);
            if (ok < key) key = ok;
        }
        if ((tx & 31) == 0) {
            int q = qbase + (ty << 3) + j;
            if (q < N) atomicMin(&g_key[q], key);
        }
    }
}

// -------- upsample (trilinear), reads g_key, writes idx output --------
__device__ __forceinline__ void axw(int i, int in, int out, int& i0, int& i1, float& f) {
    float scale = (float)in / (float)out;
    float src = fmaxf((i + 0.5f)*scale - 0.5f, 0.f);
    i0 = (int)src;
    if (i0 > in-1) i0 = in-1;
    i1 = i0 + 1; if (i1 > in-1) i1 = in-1;
    f = src - (float)i0;
}

__global__ void k_upsample(const float* __restrict__ emb, int tpn, int pn, int N,
                           float* __restrict__ idx_out) {
    int tid = blockIdx.x*256 + threadIdx.x;
    if (tid >= ZSIZE) return;
    if (tid < N) idx_out[tid] = (float)(unsigned)(g_key[tid] & 0xffffffffull);
    int c = tid & 63;            // channel in LOW bits -> coalesced gathers
    int s = tid >> 6;
    int w = s & 15, h = (s >> 4) & 15, t = (s >> 8) & 3, b = s >> 10;
    int t0,t1,h0,h1,w0,w1; float ft,fh,fw;
    axw(t, tpn,  4, t0, t1, ft);
    axw(h, pn,  16, h0, h1, fh);
    axw(w, pn,  16, w0, w1, fw);
    int ts[2]  = {t0, t1}; float twt[2] = {1.f-ft, ft};
    int hs[2]  = {h0, h1}; float hwt[2] = {1.f-fh, fh};
    int wss[2] = {w0, w1}; float wwt[2] = {1.f-fw, fw};
    int nb = b*tpn;
    float v = 0.f;
    #pragma unroll
    for (int a = 0; a < 2; a++)
        #pragma unroll
        for (int d = 0; d < 2; d++)
            #pragma unroll
            for (int e = 0; e < 2; e++) {
                float wt = twt[a]*hwt[d]*wwt[e];
                int n = ((nb + ts[a])*pn + hs[d])*pn + wss[e];
                int id = (int)(unsigned)(g_key[n] & 0xffffffffull);
                v = fmaf(wt, emb[id*64 + c], v);
            }
    g_hup[((b*64 + c)*4 + t)*256 + h*16 + w] = v;
}

// ---- conv3d 3x3x3 SAME + residual mix + accumulate + commit ----
__global__ void __launch_bounds__(256) k_conv(const float* __restrict__ z,
                                              const float* __restrict__ bq, int qi) {
    int b = blockIdx.x, t = blockIdx.y, hq = blockIdx.z;
    int tid = threadIdx.x;
    int c = tid & 63, hh = tid >> 6;
    int h = hq*4 + hh;
    __shared__ float xs[288];      // [3 t][6 h][16 w]
    __shared__ float ws[1728];     // [64 c][27 k]
    __shared__ float red[8];
    float acc[16];
    #pragma unroll
    for (int i = 0; i < 16; i++) acc[i] = 0.f;
    for (int ci = 0; ci < 64; ci++) {
        __syncthreads();
        const float* wsrc = g_Wt + (size_t)((qi*64 + ci)*64)*27;
        for (int i = tid; i < 1728; i += 256) ws[i] = wsrc[i];
        for (int i = tid; i < 288; i += 256) {
            int td = i/96, rem = i%96, hd = rem/16, wd = rem & 15;
            int tt = t + td - 1;
            int hg = hq*4 + hd - 1;
            xs[i] = (tt >= 0 && tt < 4 && hg >= 0 && hg < 16)
                      ? g_hup[((b*64 + ci)*4 + tt)*256 + hg*16 + wd] : 0.f;
        }
        __syncthreads();
        #pragma unroll
        for (int kd = 0; kd < 3; kd++) {
            #pragma unroll
            for (int kh = 0; kh < 3; kh++) {
                float r[18];
                r[0] = 0.f; r[17] = 0.f;
                const float* xrow = xs + (kd*6 + hh + kh)*16;
                #pragma unroll
                for (int i2 = 0; i2 < 16; i2++) r[i2+1] = xrow[i2];
                const float* wp = ws + c*27 + kd*9 + kh*3;
                #pragma unroll
                for (int kw = 0; kw < 3; kw++) {
                    float wv = wp[kw];
                    #pragma unroll
                    for (int w2 = 0; w2 < 16; w2++)
                        acc[w2] = fmaf(wv, r[w2+kw], acc[w2]);
                }
            }
        }
    }
    float bias = bq[qi*64 + c];
    int base = ((b*64 + c)*4 + t)*256 + h*16;
    float lsum = 0.f;
    #pragma unroll
    for (int w2 = 0; w2 < 16; w2++) {
        float hv = g_hup[base + w2];
        float val = 0.5f*hv + 0.5f*(acc[w2] + bias);
        float a = g_accu[base + w2] + val;
        g_accu[base + w2] = a;
        float d = a - z[base + w2];
        lsum = fmaf(d, d, lsum);
    }
    #pragma unroll
    for (int o = 16; o; o >>= 1) lsum += __shfl_down_sync(0xffffffffu, lsum, o);
    if ((tid & 31) == 0) red[tid >> 5] = lsum;
    __syncthreads();
    if (tid < 8) {
        float v = red[tid];
        #pragma unroll
        for (int o = 4; o; o >>= 1) v += __shfl_down_sync(0xffu, v, o);
        if (tid == 0) atomicAdd(&g_commit, v);
    }
}

// ---------------- finalization ----------------
__global__ void k_bincount() {       // last scale's keys still in g_key
    int n = blockIdx.x*256 + threadIdx.x;
    if (n < 8192) atomicAdd(&g_counts[(int)(unsigned)(g_key[n] & 0xffffffffull)], 1);
}

__global__ void k_copy(const float* __restrict__ z, float* __restrict__ out) {
    int i = blockIdx.x*256 + threadIdx.x;
    if (i < ZSIZE) out[i] = (g_accu[i] - z[i]) + z[i];
}

__global__ void k_stats(float* __restrict__ out) {
    int tid = threadIdx.x;
    float ent = 0.f; int cnt = 0;
    for (int i = tid; i < NCODES; i += 256) {
        float p = (float)g_counts[i] * (1.0f/8192.0f);
        out[OFF_USAGE + i] = p;
        ent += p * logf(p + 1e-10f);
        if (p > (1.0f/16384.0f)) cnt++;
    }
    __shared__ float se[256];
    __shared__ int   sc[256];
    se[tid] = ent; sc[tid] = cnt;
    __syncthreads();
    for (int o = 128; o; o >>= 1) {
        if (tid < o) { se[tid] += se[tid+o]; sc[tid] += sc[tid+o]; }
        __syncthreads();
    }
    if (tid == 0) {
        out[OFF_COMMIT] = g_commit * (0.25f/524288.0f) * 0.1f;
        out[OFF_PERP]   = expf(-se[0]);
        out[OFF_AVG]    = (float)sc[0] / 16384.0f;
    }
}

extern "C" void kernel_launch(void* const* d_in, const int* in_sizes, int n_in,
                              void* d_out, int out_size) {
    const float* z   = nullptr;
    const float* emb = nullptr;
    const float* Wq  = nullptr;
    const float* bq  = nullptr;
    for (int i = 0; i < n_in; i++) {
        switch (in_sizes[i]) {
            case 524288:  z   = (const float*)d_in[i]; break;
            case 1048576: emb = (const float*)d_in[i]; break;
            case 442368:  Wq  = (const float*)d_in[i]; break;
            case 256:     bq  = (const float*)d_in[i]; break;
        }
    }
    float* out = (float*)d_out;

    k_prep_emb<<<(CEMB*NCODES + 255)/256, 256>>>(emb);
    k_esq<<<(NCODES + 255)/256, 256>>>(emb);
    k_prep_w<<<(4*64*64*27 + 255)/256, 256>>>(Wq);
    k_zero<<<(ZSIZE + 255)/256, 256>>>();

    static const int TPN[10] = {1,1,2,2,2,4,4,4,4,4};
    static const int VPN[10] = {1,2,3,4,5,6,8,10,13,16};
    static const int QIA[10] = {0,0,1,1,1,2,2,3,3,3};

    int off = OFF_IDX;
    for (int si = 0; si < 10; si++) {
        int tpn = TPN[si], pn = VPN[si];
        int N = BB * tpn * pn * pn;
        k_pool<<<(N*64 + 255)/256, 256>>>(z, tpn, pn, N);
        dim3 gnn(32, (N + 31)/32), bnn(64, 4);
        k_nn<<<gnn, bnn>>>(N);
        k_upsample<<<(ZSIZE + 255)/256, 256>>>(emb, tpn, pn, N, out + off);
        off += N;
        k_conv<<<dim3(8,4,4), 256>>>(z, bq, QIA[si]);
    }
    k_bincount<<<32, 256>>>();
    k_copy<<<(ZSIZE + 255)/256, 256>>>(z, out);
    k_stats<<<1, 256>>>(out);
}

// round 5
// speedup vs baseline: 1.4837x; 1.4124x over previous
#include <cuda_runtime.h>
#include <math.h>

#define NCODES 16384
#define CEMB   64
#define BB     8
#define ZSIZE  (BB*CEMB*4*16*16)   /* 524288 */
#define MAXN   8192

#define OFF_COMMIT 524288
#define OFF_PERP   524289
#define OFF_AVG    524290
#define OFF_USAGE  524291
#define OFF_IDX    540675

typedef unsigned long long ull;

__device__ float g_accu[ZSIZE];
__device__ float g_hup[ZSIZE];
__device__ float g_q[MAXN*CEMB];
__device__ ull   g_key[MAXN];
__device__ float g_embT[CEMB*NCODES];
__device__ float g_esq[NCODES];
__device__ float g_Wt[4*64*64*27];
__device__ float g_commit;
__device__ int   g_counts[NCODES];

#define FMA2(d,a,b) asm("fma.rn.f32x2 %0, %1, %2, %3;" : "=l"(d) : "l"(a), "l"(b), "l"(d))

// ---------------- setup ----------------
__global__ void k_prep_emb(const float* __restrict__ emb) {
    int tid = blockIdx.x*256 + threadIdx.x;
    if (tid < CEMB*NCODES) {
        int k = tid >> 14, c = tid & (NCODES-1);
        g_embT[tid] = emb[c*CEMB + k];
    }
}

__global__ void k_esq(const float* __restrict__ emb) {
    int c = blockIdx.x*256 + threadIdx.x;
    if (c < NCODES) {
        const float4* p = reinterpret_cast<const float4*>(emb + c*CEMB);
        float s = 0.f;
        #pragma unroll
        for (int i = 0; i < 16; i++) {
            float4 v = p[i];
            s += v.x*v.x + v.y*v.y + v.z*v.z + v.w*v.w;
        }
        g_esq[c] = s;
    }
}

__global__ void k_prep_w(const float* __restrict__ Wq) {
    int tid = blockIdx.x*256 + threadIdx.x;
    if (tid < 4*64*64*27) {
        int k  = tid % 27;
        int t2 = tid / 27;
        int c  = t2 % 64;
        int t3 = t2 / 64;
        int ci = t3 % 64;
        int q  = t3 / 64;
        g_Wt[tid] = Wq[((q*64 + c)*64 + ci)*27 + k];
    }
}

__global__ void k_zero() {
    int tid = blockIdx.x*256 + threadIdx.x;
    if (tid < ZSIZE) g_accu[tid] = 0.f;
    if (tid < NCODES) g_counts[tid] = 0;
    if (tid == 0) g_commit = 0.f;
}

// -------- per-scale: pool (z - accu) -> queries [N][64]; also init keys --------
__global__ void k_pool(const float* __restrict__ z, int tpn, int pn, int N) {
    int tid = blockIdx.x*256 + threadIdx.x;
    if (tid >= N*64) return;
    int c = tid & 63;
    int n = tid >> 6;
    if (c == 0) g_key[n] = 0xFFFFFFFFFFFFFFFFull;
    int x = n % pn;
    int v = (n/pn) % pn;
    int r2 = n/(pn*pn);
    int u = r2 % tpn;
    int b = r2 / tpn;
    int sT = (u*4)/tpn,  eT = ((u+1)*4  + tpn-1)/tpn;
    int sH = (v*16)/pn,  eH = ((v+1)*16 + pn-1)/pn;
    int sW = (x*16)/pn,  eW = ((x+1)*16 + pn-1)/pn;
    const float* zp = z      + (b*64 + c)*1024;
    const float* ap = g_accu + (b*64 + c)*1024;
    float sum = 0.f;
    for (int t = sT; t < eT; t++)
        for (int h = sH; h < eH; h++)
            for (int w = sW; w < eW; w++) {
                int o = t*256 + h*16 + w;
                sum += zp[o] - ap[o];
            }
    float inv = (1.f/(float)(eT-sT))*(1.f/(float)(eH-sH))*(1.f/(float)(eW-sW));
    g_q[n*64 + c] = sum * inv;
}

// -------- NN search: 32 queries x 512 codes per block, packed f32x2 FMA --------
__global__ void __launch_bounds__(256, 2) k_nn(int N) {
    int tx = threadIdx.x;            // 0..63 (8 codes each, as 4 f32x2 pairs)
    int ty = threadIdx.y;            // 0..3  (8 queries each)
    int qbase = blockIdx.y << 5;
    int cbase = (blockIdx.x << 9) + (tx << 3);
    __shared__ __align__(16) ull qs[32*64];   // each q value duplicated into both lanes
    int tid = ty*64 + tx;
    for (int i = tid; i < 2048; i += 256) {
        int qr = qbase + (i >> 6);
        float v = (qr < N) ? g_q[qr*64 + (i & 63)] : 0.f;
        unsigned u = __float_as_uint(v);
        qs[i] = ((ull)u << 32) | u;
    }
    __syncthreads();
    ull acc[8][4];
    #pragma unroll
    for (int j = 0; j < 8; j++)
        #pragma unroll
        for (int cc = 0; cc < 4; cc++) acc[j][cc] = 0ull;
    const ulonglong2* e2 = reinterpret_cast<const ulonglong2*>(g_embT);
    // row k: 16384 floats = 4096 ulonglong2; this thread's 8 codes = 2 ulonglong2
    int coff = (blockIdx.x << 7) + (tx << 1);
    const ull* qb = qs + (ty << 3)*64;
    #pragma unroll 2
    for (int k = 0; k < 64; k += 2) {
        ulonglong2 ea0 = e2[(k << 12) + coff];
        ulonglong2 eb0 = e2[(k << 12) + coff + 1];
        ulonglong2 ea1 = e2[((k+1) << 12) + coff];
        ulonglong2 eb1 = e2[((k+1) << 12) + coff + 1];
        #pragma unroll
        for (int j = 0; j < 8; j++) {
            ull q0 = qb[j*64 + k];
            ull q1 = qb[j*64 + k + 1];
            FMA2(acc[j][0], q0, ea0.x);
            FMA2(acc[j][1], q0, ea0.y);
            FMA2(acc[j][2], q0, eb0.x);
            FMA2(acc[j][3], q0, eb0.y);
            FMA2(acc[j][0], q1, ea1.x);
            FMA2(acc[j][1], q1, ea1.y);
            FMA2(acc[j][2], q1, eb1.x);
            FMA2(acc[j][3], q1, eb1.y);
        }
    }
    const float4* s4 = reinterpret_cast<const float4*>(g_esq);
    float4 qa = s4[cbase >> 2];
    float4 qbv = s4[(cbase >> 2) + 1];
    float es[8] = {qa.x, qa.y, qa.z, qa.w, qbv.x, qbv.y, qbv.z, qbv.w};
    #pragma unroll
    for (int j = 0; j < 8; j++) {
        float best = 3.4e38f; int bi = 0;
        #pragma unroll
        for (int cc = 0; cc < 4; cc++) {
            float d0 = __uint_as_float((unsigned)(acc[j][cc] & 0xffffffffull));
            float d1 = __uint_as_float((unsigned)(acc[j][cc] >> 32));
            float s0 = fmaf(-2.f, d0, es[2*cc]);
            float s1 = fmaf(-2.f, d1, es[2*cc+1]);
            if (s0 < best) { best = s0; bi = cbase + 2*cc; }
            if (s1 < best) { best = s1; bi = cbase + 2*cc + 1; }
        }
        unsigned ub = __float_as_uint(best);
        ub = (ub & 0x80000000u) ? ~ub : (ub | 0x80000000u);
        ull key = ((ull)ub << 32) | (unsigned)bi;
        #pragma unroll
        for (int o = 16; o; o >>= 1) {
            ull ok = __shfl_down_sync(0xffffffffu, key, o);
            if (ok < key) key = ok;
        }
        if ((tx & 31) == 0) {
            int q = qbase + (ty << 3) + j;
            if (q < N) atomicMin(&g_key[q], key);
        }
    }
}

// -------- upsample (trilinear), reads g_key, writes idx output --------
__device__ __forceinline__ void axw(int i, int in, int out, int& i0, int& i1, float& f) {
    float scale = (float)in / (float)out;
    float src = fmaxf((i + 0.5f)*scale - 0.5f, 0.f);
    i0 = (int)src;
    if (i0 > in-1) i0 = in-1;
    i1 = i0 + 1; if (i1 > in-1) i1 = in-1;
    f = src - (float)i0;
}

__global__ void k_upsample(const float* __restrict__ emb, int tpn, int pn, int N,
                           float* __restrict__ idx_out) {
    int tid = blockIdx.x*256 + threadIdx.x;
    if (tid >= ZSIZE) return;
    if (tid < N) idx_out[tid] = (float)(unsigned)(g_key[tid] & 0xffffffffull);
    int c = tid & 63;
    int s = tid >> 6;
    int w = s & 15, h = (s >> 4) & 15, t = (s >> 8) & 3, b = s >> 10;
    int t0,t1,h0,h1,w0,w1; float ft,fh,fw;
    axw(t, tpn,  4, t0, t1, ft);
    axw(h, pn,  16, h0, h1, fh);
    axw(w, pn,  16, w0, w1, fw);
    int ts[2]  = {t0, t1}; float twt[2] = {1.f-ft, ft};
    int hs[2]  = {h0, h1}; float hwt[2] = {1.f-fh, fh};
    int wss[2] = {w0, w1}; float wwt[2] = {1.f-fw, fw};
    int nb = b*tpn;
    float v = 0.f;
    #pragma unroll
    for (int a = 0; a < 2; a++)
        #pragma unroll
        for (int d = 0; d < 2; d++)
            #pragma unroll
            for (int e = 0; e < 2; e++) {
                float wt = twt[a]*hwt[d]*wwt[e];
                int n = ((nb + ts[a])*pn + hs[d])*pn + wss[e];
                int id = (int)(unsigned)(g_key[n] & 0xffffffffull);
                v = fmaf(wt, emb[id*64 + c], v);
            }
    g_hup[((b*64 + c)*4 + t)*256 + h*16 + w] = v;
}

// ---- conv3d 3x3x3 SAME + residual mix + accumulate + commit (ci batched x4) ----
__global__ void __launch_bounds__(256) k_conv(const float* __restrict__ z,
                                              const float* __restrict__ bq, int qi) {
    int b = blockIdx.x, t = blockIdx.y, hq = blockIdx.z;
    int tid = threadIdx.x;
    int c = tid & 63, hh = tid >> 6;
    int h = hq*4 + hh;
    __shared__ float ws[4][1728];   // 4 ci batches of [64 c][27 k]
    __shared__ float xs[4][288];    // 4 ci batches of [3 t][6 h][16 w]
    __shared__ float red[8];
    float acc[16];
    #pragma unroll
    for (int i = 0; i < 16; i++) acc[i] = 0.f;
    for (int cb = 0; cb < 64; cb += 4) {
        __syncthreads();
        const float* wsrc = g_Wt + (size_t)(qi*64 + cb)*1728;
        for (int i = tid; i < 4*1728; i += 256) ws[0][i] = wsrc[i];
        for (int i = tid; i < 4*288; i += 256) {
            int cib = i / 288, r = i % 288;
            int td = r/96, rem = r%96, hd = rem/16, wd = rem & 15;
            int tt = t + td - 1;
            int hg = hq*4 + hd - 1;
            xs[cib][r] = (tt >= 0 && tt < 4 && hg >= 0 && hg < 16)
                      ? g_hup[((b*64 + cb + cib)*4 + tt)*256 + hg*16 + wd] : 0.f;
        }
        __syncthreads();
        #pragma unroll
        for (int cib = 0; cib < 4; cib++) {
            #pragma unroll
            for (int kd = 0; kd < 3; kd++) {
                #pragma unroll
                for (int kh = 0; kh < 3; kh++) {
                    float r[18];
                    r[0] = 0.f; r[17] = 0.f;
                    const float* xrow = xs[cib] + (kd*6 + hh + kh)*16;
                    #pragma unroll
                    for (int i2 = 0; i2 < 16; i2++) r[i2+1] = xrow[i2];
                    const float* wp = ws[cib] + c*27 + kd*9 + kh*3;
                    #pragma unroll
                    for (int kw = 0; kw < 3; kw++) {
                        float wv = wp[kw];
                        #pragma unroll
                        for (int w2 = 0; w2 < 16; w2++)
                            acc[w2] = fmaf(wv, r[w2+kw], acc[w2]);
                    }
                }
            }
        }
    }
    float bias = bq[qi*64 + c];
    int base = ((b*64 + c)*4 + t)*256 + h*16;
    float lsum = 0.f;
    #pragma unroll
    for (int w2 = 0; w2 < 16; w2++) {
        float hv = g_hup[base + w2];
        float val = 0.5f*hv + 0.5f*(acc[w2] + bias);
        float a = g_accu[base + w2] + val;
        g_accu[base + w2] = a;
        float d = a - z[base + w2];
        lsum = fmaf(d, d, lsum);
    }
    #pragma unroll
    for (int o = 16; o; o >>= 1) lsum += __shfl_down_sync(0xffffffffu, lsum, o);
    if ((tid & 31) == 0) red[tid >> 5] = lsum;
    __syncthreads();
    if (tid < 8) {
        float v = red[tid];
        #pragma unroll
        for (int o = 4; o; o >>= 1) v += __shfl_down_sync(0xffu, v, o);
        if (tid == 0) atomicAdd(&g_commit, v);
    }
}

// ---------------- finalization ----------------
__global__ void k_bincount() {
    int n = blockIdx.x*256 + threadIdx.x;
    if (n < 8192) atomicAdd(&g_counts[(int)(unsigned)(g_key[n] & 0xffffffffull)], 1);
}

__global__ void k_copy(const float* __restrict__ z, float* __restrict__ out) {
    int i = blockIdx.x*256 + threadIdx.x;
    if (i < ZSIZE) out[i] = (g_accu[i] - z[i]) + z[i];
}

__global__ void k_stats(float* __restrict__ out) {
    int tid = threadIdx.x;
    float ent = 0.f; int cnt = 0;
    for (int i = tid; i < NCODES; i += 256) {
        float p = (float)g_counts[i] * (1.0f/8192.0f);
        out[OFF_USAGE + i] = p;
        ent += p * logf(p + 1e-10f);
        if (p > (1.0f/16384.0f)) cnt++;
    }
    __shared__ float se[256];
    __shared__ int   sc[256];
    se[tid] = ent; sc[tid] = cnt;
    __syncthreads();
    for (int o = 128; o; o >>= 1) {
        if (tid < o) { se[tid] += se[tid+o]; sc[tid] += sc[tid+o]; }
        __syncthreads();
    }
    if (tid == 0) {
        out[OFF_COMMIT] = g_commit * (0.25f/524288.0f) * 0.1f;
        out[OFF_PERP]   = expf(-se[0]);
        out[OFF_AVG]    = (float)sc[0] / 16384.0f;
    }
}

extern "C" void kernel_launch(void* const* d_in, const int* in_sizes, int n_in,
                              void* d_out, int out_size) {
    const float* z   = nullptr;
    const float* emb = nullptr;
    const float* Wq  = nullptr;
    const float* bq  = nullptr;
    for (int i = 0; i < n_in; i++) {
        switch (in_sizes[i]) {
            case 524288:  z   = (const float*)d_in[i]; break;
            case 1048576: emb = (const float*)d_in[i]; break;
            case 442368:  Wq  = (const float*)d_in[i]; break;
            case 256:     bq  = (const float*)d_in[i]; break;
        }
    }
    float* out = (float*)d_out;

    k_prep_emb<<<(CEMB*NCODES + 255)/256, 256>>>(emb);
    k_esq<<<(NCODES + 255)/256, 256>>>(emb);
    k_prep_w<<<(4*64*64*27 + 255)/256, 256>>>(Wq);
    k_zero<<<(ZSIZE + 255)/256, 256>>>();

    static const int TPN[10] = {1,1,2,2,2,4,4,4,4,4};
    static const int VPN[10] = {1,2,3,4,5,6,8,10,13,16};
    static const int QIA[10] = {0,0,1,1,1,2,2,3,3,3};

    int off = OFF_IDX;
    for (int si = 0; si < 10; si++) {
        int tpn = TPN[si], pn = VPN[si];
        int N = BB * tpn * pn * pn;
        k_pool<<<(N*64 + 255)/256, 256>>>(z, tpn, pn, N);
        dim3 gnn(32, (N + 31)/32), bnn(64, 4);
        k_nn<<<gnn, bnn>>>(N);
        k_upsample<<<(ZSIZE + 255)/256, 256>>>(emb, tpn, pn, N, out + off);
        off += N;
        k_conv<<<dim3(8,4,4), 256>>>(z, bq, QIA[si]);
    }
    k_bincount<<<32, 256>>>();
    k_copy<<<(ZSIZE + 255)/256, 256>>>(z, out);
    k_stats<<<1, 256>>>(out);
}